// round 15
// baseline (speedup 1.0000x reference)
#include <cuda_runtime.h>
#include <cuda_bf16.h>
#include <cstddef>

// out[b,n] = sum_s x[b,n,s]*W[n,s] + bias[n]
// B=128, N=1024, S=2048, fp32. Pure HBM-streaming reduction.
// One warp computes BM=4 batches for a single neuron n, reusing the W row
// (held in registers per-chunk) across the 4 x rows -> 4x less W L2 traffic.

#define B_DIM 128
#define N_DIM 1024
#define S_DIM 2048
#define BM 4                         // batches per warp
#define WARPS_TOTAL (N_DIM * (B_DIM / BM))   // 32768
#define THREADS_PER_BLOCK 256
#define WARPS_PER_BLOCK (THREADS_PER_BLOCK / 32)
#define NUM_BLOCKS (WARPS_TOTAL / WARPS_PER_BLOCK)  // 4096

__global__ void __launch_bounds__(THREADS_PER_BLOCK)
single_sample_linear_kernel(const float* __restrict__ x,
                            const float* __restrict__ W,
                            const float* __restrict__ bias,
                            float* __restrict__ out) {
    const int warp_global = (blockIdx.x * THREADS_PER_BLOCK + threadIdx.x) >> 5;
    const int lane = threadIdx.x & 31;

    // Consecutive warps -> consecutive n (contiguous 8KB x rows per block),
    // same batch group.
    const int n  = warp_global & (N_DIM - 1);
    const int bg = warp_global >> 10;          // batch group, 0..31

    const float* __restrict__ Wrow = W + (size_t)n * S_DIM;
    const size_t xbase = ((size_t)(bg * BM) * N_DIM + n) * S_DIM;

    float acc0 = 0.f, acc1 = 0.f, acc2 = 0.f, acc3 = 0.f;

    // S/(32 lanes * 4 per float4) = 16 chunks per lane.
    #pragma unroll 4
    for (int i = 0; i < S_DIM / (32 * 4); ++i) {
        const int off = (i * 32 + lane) * 4;
        const float4 w4 = *reinterpret_cast<const float4*>(Wrow + off);

        const float4 x0 = *reinterpret_cast<const float4*>(x + xbase + (size_t)0 * N_DIM * S_DIM + off);
        const float4 x1 = *reinterpret_cast<const float4*>(x + xbase + (size_t)1 * N_DIM * S_DIM + off);
        const float4 x2 = *reinterpret_cast<const float4*>(x + xbase + (size_t)2 * N_DIM * S_DIM + off);
        const float4 x3 = *reinterpret_cast<const float4*>(x + xbase + (size_t)3 * N_DIM * S_DIM + off);

        acc0 += x0.x * w4.x + x0.y * w4.y + x0.z * w4.z + x0.w * w4.w;
        acc1 += x1.x * w4.x + x1.y * w4.y + x1.z * w4.z + x1.w * w4.w;
        acc2 += x2.x * w4.x + x2.y * w4.y + x2.z * w4.z + x2.w * w4.w;
        acc3 += x3.x * w4.x + x3.y * w4.y + x3.z * w4.z + x3.w * w4.w;
    }

    // Warp butterfly reduction for each accumulator.
    #pragma unroll 5
    for (int o = 16; o > 0; o >>= 1) {
        acc0 += __shfl_xor_sync(0xffffffffu, acc0, o);
        acc1 += __shfl_xor_sync(0xffffffffu, acc1, o);
        acc2 += __shfl_xor_sync(0xffffffffu, acc2, o);
        acc3 += __shfl_xor_sync(0xffffffffu, acc3, o);
    }

    if (lane == 0) {
        const float bv = bias[n];
        const int b0 = bg * BM;
        out[(size_t)(b0 + 0) * N_DIM + n] = acc0 + bv;
        out[(size_t)(b0 + 1) * N_DIM + n] = acc1 + bv;
        out[(size_t)(b0 + 2) * N_DIM + n] = acc2 + bv;
        out[(size_t)(b0 + 3) * N_DIM + n] = acc3 + bv;
    }
}

extern "C" void kernel_launch(void* const* d_in, const int* in_sizes, int n_in,
                              void* d_out, int out_size) {
    const float* x    = (const float*)d_in[0];   // [B, N, S]
    const float* W    = (const float*)d_in[1];   // [N, S]
    const float* bias = (const float*)d_in[2];   // [N]
    float* out = (float*)d_out;                  // [B, N]

    single_sample_linear_kernel<<<NUM_BLOCKS, THREADS_PER_BLOCK>>>(x, W, bias, out);
}